// round 5
// baseline (speedup 1.0000x reference)
#include <cuda_runtime.h>
#include <math.h>
#include <stdint.h>

// Problem constants
#define CB   8          // batch
#define CSEQ 2048
#define CT   2049       // SEQ + CLS
#define CV   4096       // vocab
#define CD   1024       // model dim
#define CH   16         // heads
#define CDH  64         // head dim
#define CNL  8          // layers
#define CFF  4096       // ff dim
#define CM   (CB*CT)    // 16392 rows

// ---------------- scratch (device globals; no allocation allowed) ----------------
__device__ float g_x  [(size_t)CB*CT*CD];
__device__ float g_q  [(size_t)CB*CT*CD];
__device__ float g_k  [(size_t)CB*CT*CD];
__device__ float g_v  [(size_t)CB*CT*CD];
__device__ float g_tmp[(size_t)CB*CT*CD];
__device__ float g_ff [(size_t)CB*CT*CFF];
__device__ float g_kvp [(size_t)CB*CH*8*CDH*CDH];   // partial KV per seq-chunk
__device__ float g_ksp [(size_t)CB*CH*8*CDH];       // partial Ksum per seq-chunk
__device__ float g_kv  [(size_t)CB*CH*CDH*CDH];
__device__ float g_ksum[(size_t)CB*CH*CDH];
__device__ float g_cls [(size_t)CB*CD];

// ---------------- helpers ----------------
__device__ __forceinline__ float geluf(float v) {
    return 0.5f * v * (1.0f + erff(v * 0.70710678118654752f));
}

// ---------------- tiled SGEMM: C[M,N] = A[M,K] @ B[K,N] (+epilogue) ----------------
// EPI: 0 = +bias ; 1 = gelu(.+bias) ; 2 = embedding (+bias +pos, remap rows n*2049+s+1)
template<int EPI>
__global__ __launch_bounds__(256, 2) void sgemm(
    const float* __restrict__ A, const float* __restrict__ Bm,
    const float* __restrict__ bias, const float* __restrict__ pos,
    float* __restrict__ C, int M, int N, int K)
{
    __shared__ float As[8][128];
    __shared__ float Bs[8][128];
    const int t = threadIdx.x;
    const int rowBase = blockIdx.y * 128;
    const int colBase = blockIdx.x * 128;
    const int aRow = t >> 1;
    const int aCol = (t & 1) << 2;
    const int bRow = t >> 5;
    const int bCol = (t & 31) << 2;
    const int tx = t & 15, ty = t >> 4;

    float acc[8][8];
#pragma unroll
    for (int i = 0; i < 8; i++)
#pragma unroll
        for (int j = 0; j < 8; j++) acc[i][j] = 0.f;

    const bool aValid = (rowBase + aRow) < M;
    const float* Ap = A + (size_t)(rowBase + aRow) * K + aCol;
    const float* Bp = Bm + (size_t)bRow * N + colBase + bCol;

    for (int k0 = 0; k0 < K; k0 += 8) {
        float4 av = aValid ? *(const float4*)(Ap + k0) : make_float4(0.f, 0.f, 0.f, 0.f);
        As[aCol + 0][aRow] = av.x;
        As[aCol + 1][aRow] = av.y;
        As[aCol + 2][aRow] = av.z;
        As[aCol + 3][aRow] = av.w;
        *(float4*)&Bs[bRow][bCol] = *(const float4*)(Bp + (size_t)k0 * N);
        __syncthreads();
#pragma unroll
        for (int k = 0; k < 8; k++) {
            float ra[8], rb[8];
            *(float4*)&ra[0] = *(const float4*)&As[k][ty * 4];
            *(float4*)&ra[4] = *(const float4*)&As[k][ty * 4 + 64];
            *(float4*)&rb[0] = *(const float4*)&Bs[k][tx * 4];
            *(float4*)&rb[4] = *(const float4*)&Bs[k][tx * 4 + 64];
#pragma unroll
            for (int i = 0; i < 8; i++)
#pragma unroll
                for (int j = 0; j < 8; j++) acc[i][j] += ra[i] * rb[j];
        }
        __syncthreads();
    }

#pragma unroll
    for (int i = 0; i < 8; i++) {
        int r = rowBase + ty * 4 + ((i < 4) ? i : 64 + i - 4);
        if (r >= M) continue;
        size_t outRow = (size_t)r;
        const float* posRow = nullptr;
        if (EPI == 2) {
            int n = r >> 11;        // / 2048
            int s = r & 2047;
            outRow = (size_t)n * CT + s + 1;
            posRow = pos + (size_t)(s + 1) * CD;
        }
#pragma unroll
        for (int jh = 0; jh < 2; jh++) {
            int c = colBase + tx * 4 + jh * 64;
            float4 v;
            v.x = acc[i][jh * 4 + 0] + bias[c + 0];
            v.y = acc[i][jh * 4 + 1] + bias[c + 1];
            v.z = acc[i][jh * 4 + 2] + bias[c + 2];
            v.w = acc[i][jh * 4 + 3] + bias[c + 3];
            if (EPI == 1) { v.x = geluf(v.x); v.y = geluf(v.y); v.z = geluf(v.z); v.w = geluf(v.w); }
            if (EPI == 2) { v.x += posRow[c + 0]; v.y += posRow[c + 1]; v.z += posRow[c + 2]; v.w += posRow[c + 3]; }
            *(float4*)&C[outRow * N + c] = v;
        }
    }
}

// ---------------- CLS row: x[n,0,:] = We[V-1,:] + be + pos[0,:] ----------------
__global__ void cls_kernel(const float* __restrict__ We, const float* __restrict__ be,
                           const float* __restrict__ pos, float* __restrict__ x)
{
    int idx = blockIdx.x * 256 + threadIdx.x;
    if (idx >= CB * CD) return;
    int n = idx >> 10, c = idx & 1023;
    x[(size_t)n * CT * CD + c] = We[(size_t)(CV - 1) * CD + c] + be[c] + pos[c];
}

// ---------------- RoPE + phi(x)=elu(x)+1 on q and k, in place ----------------
__global__ void rope_phi_kernel(float* __restrict__ q, float* __restrict__ k)
{
    int idx = blockIdx.x * 256 + threadIdx.x;           // over B*T*H*32
    if (idx >= CB * CT * CH * 32) return;
    int j  = idx & 31;
    int h  = (idx >> 5) & 15;
    int nt = idx >> 9;                                  // n*T + t
    int tt = nt % CT;
    int n  = nt / CT;
    size_t base = (((size_t)n * CT + tt) * CH + h) * CDH;
    float invf = 1.0f / powf(10000.0f, (float)(2 * j) / (float)CDH);
    float ang = (float)tt * invf;
    float c, s;
    sincosf(ang, &s, &c);

    float q1 = q[base + j], q2 = q[base + j + 32];
    float qa = q1 * c - q2 * s;
    float qb = q2 * c + q1 * s;
    q[base + j]      = (qa > 0.f) ? (qa + 1.f) : expf(qa);
    q[base + j + 32] = (qb > 0.f) ? (qb + 1.f) : expf(qb);

    float k1 = k[base + j], k2 = k[base + j + 32];
    float ka = k1 * c - k2 * s;
    float kb = k2 * c + k1 * s;
    k[base + j]      = (ka > 0.f) ? (ka + 1.f) : expf(ka);
    k[base + j + 32] = (kb > 0.f) ? (kb + 1.f) : expf(kb);
}

// ---------------- KV partial: per (n,h,chunk): KV += Kf^T @ V over seq chunk ----------------
__global__ __launch_bounds__(256) void kv_partial(const float* __restrict__ Kf, const float* __restrict__ Vf,
                                                  float* __restrict__ kvp, float* __restrict__ ksp)
{
    int nh = blockIdx.x, ch = blockIdx.y;
    int n = nh >> 4, h = nh & 15;
    int s0 = ch * 257;
    int s1 = min(s0 + 257, CT);
    int t = threadIdx.x;
    int d0 = t >> 2;
    int mq = (t & 3) << 4;
    __shared__ float sk[8][64];
    __shared__ float sv[8][64];
    float acc[16];
#pragma unroll
    for (int j = 0; j < 16; j++) acc[j] = 0.f;
    float ks = 0.f;

    for (int s = s0; s < s1; s += 8) {
        int nr = min(8, s1 - s);
        for (int i = t; i < nr * 64; i += 256) {
            int rr = i >> 6, dd = i & 63;
            size_t off = (((size_t)n * CT + (s + rr)) * CH + h) * CDH + dd;
            sk[rr][dd] = Kf[off];
            sv[rr][dd] = Vf[off];
        }
        __syncthreads();
        for (int rr = 0; rr < nr; rr++) {
            float kd = sk[rr][d0];
            ks += kd;
            const float4* v4 = (const float4*)&sv[rr][mq];
            float4 v0 = v4[0], v1 = v4[1], v2 = v4[2], v3 = v4[3];
            acc[0]  += kd * v0.x;  acc[1]  += kd * v0.y;  acc[2]  += kd * v0.z;  acc[3]  += kd * v0.w;
            acc[4]  += kd * v1.x;  acc[5]  += kd * v1.y;  acc[6]  += kd * v1.z;  acc[7]  += kd * v1.w;
            acc[8]  += kd * v2.x;  acc[9]  += kd * v2.y;  acc[10] += kd * v2.z;  acc[11] += kd * v2.w;
            acc[12] += kd * v3.x;  acc[13] += kd * v3.y;  acc[14] += kd * v3.z;  acc[15] += kd * v3.w;
        }
        __syncthreads();
    }
    size_t ob = ((size_t)nh * 8 + ch) * (CDH * CDH) + (size_t)d0 * CDH + mq;
#pragma unroll
    for (int j = 0; j < 16; j++) kvp[ob + j] = acc[j];
    if ((t & 3) == 0) ksp[((size_t)nh * 8 + ch) * CDH + d0] = ks;
}

// ---------------- deterministic reduce of the 8 chunks ----------------
__global__ void kv_reduce(const float* __restrict__ kvp, const float* __restrict__ ksp,
                          float* __restrict__ kv, float* __restrict__ ksum)
{
    int idx = blockIdx.x * 256 + threadIdx.x;
    const int NKV = CB * CH * CDH * CDH;
    if (idx < NKV) {
        int nh = idx >> 12, r = idx & 4095;
        float s = 0.f;
        for (int c = 0; c < 8; c++) s += kvp[((size_t)nh * 8 + c) * (CDH * CDH) + r];
        kv[idx] = s;
    } else if (idx < NKV + CB * CH * CDH) {
        int i2 = idx - NKV;
        int nh = i2 >> 6, r = i2 & 63;
        float s = 0.f;
        for (int c = 0; c < 8; c++) s += ksp[((size_t)nh * 8 + c) * CDH + r];
        ksum[i2] = s;
    }
}

// ---------------- attn: out[t,m] = (Qf[t,:] @ KV[:,m]) / (Qf[t,:]·Ksum + eps) ----------------
__global__ __launch_bounds__(256) void attn_kernel(const float* __restrict__ Qf, const float* __restrict__ kv,
                                                   const float* __restrict__ ksum, float* __restrict__ out)
{
    int nh = blockIdx.x, ch = blockIdx.y;
    int n = nh >> 4, h = nh & 15;
    int t = threadIdx.x;
    __shared__ float skvt[64][68];   // transposed, padded: skvt[m][d] = KV[d][m]
    __shared__ float sks[64];
    __shared__ float sq[4][64];
    for (int i = t; i < 4096; i += 256) {
        int d = i >> 6, m = i & 63;
        skvt[m][d] = kv[(size_t)nh * 4096 + i];
    }
    if (t < 64) sks[t] = ksum[(size_t)nh * 64 + t];
    __syncthreads();

    int g = t >> 6, m = t & 63;
    int s0 = ch * 257;
    int s1 = min(s0 + 257, CT);
    for (int tt = s0; tt < s1; tt += 4) {
        int nr = min(4, s1 - tt);
        if (t < nr * 64)
            sq[t >> 6][t & 63] = Qf[(((size_t)n * CT + (tt + (t >> 6))) * CH + h) * CDH + (t & 63)];
        __syncthreads();
        if (g < nr) {
            float sm = 0.f, sz = 0.f;
#pragma unroll
            for (int d = 0; d < 64; d += 4) {
                float4 q4 = *(const float4*)&sq[g][d];
                float4 k4 = *(const float4*)&skvt[m][d];
                float4 z4 = *(const float4*)&sks[d];
                sm += q4.x * k4.x + q4.y * k4.y + q4.z * k4.z + q4.w * k4.w;
                sz += q4.x * z4.x + q4.y * z4.y + q4.z * z4.z + q4.w * z4.w;
            }
            out[(((size_t)n * CT + (tt + g)) * CH + h) * CDH + m] = sm / (sz + 1e-6f);
        }
        __syncthreads();
    }
}

// ---------------- fused residual + LayerNorm (in place on x) ----------------
__global__ __launch_bounds__(256) void ln_kernel(float* __restrict__ x, const float* __restrict__ res,
                                                 const float* __restrict__ g, const float* __restrict__ b)
{
    int row = blockIdx.x;
    int t = threadIdx.x;
    size_t base = (size_t)row * CD + t * 4;
    float4 a = *(const float4*)(x + base);
    float4 r = *(const float4*)(res + base);
    a.x += r.x; a.y += r.y; a.z += r.z; a.w += r.w;
    float s  = a.x + a.y + a.z + a.w;
    float ss = a.x * a.x + a.y * a.y + a.z * a.z + a.w * a.w;
#pragma unroll
    for (int o = 16; o > 0; o >>= 1) {
        s  += __shfl_xor_sync(0xffffffffu, s,  o);
        ss += __shfl_xor_sync(0xffffffffu, ss, o);
    }
    __shared__ float sh[18];
    int w = t >> 5;
    if ((t & 31) == 0) { sh[w] = s; sh[8 + w] = ss; }
    __syncthreads();
    if (t == 0) {
        float S = 0.f, SS = 0.f;
        for (int i = 0; i < 8; i++) { S += sh[i]; SS += sh[8 + i]; }
        float m = S * (1.f / CD);
        sh[16] = m;
        sh[17] = rsqrtf(SS * (1.f / CD) - m * m + 1e-5f);
    }
    __syncthreads();
    float m = sh[16], inv = sh[17];
    float4 gg = *(const float4*)(g + t * 4);
    float4 bb = *(const float4*)(b + t * 4);
    float4 o;
    o.x = (a.x - m) * inv * gg.x + bb.x;
    o.y = (a.y - m) * inv * gg.y + bb.y;
    o.z = (a.z - m) * inv * gg.z + bb.z;
    o.w = (a.w - m) * inv * gg.w + bb.w;
    *(float4*)(x + base) = o;
}

// ---------------- final LN on the 8 CLS rows ----------------
__global__ __launch_bounds__(256) void ln_cls_kernel(const float* __restrict__ x, const float* __restrict__ g,
                                                     const float* __restrict__ b, float* __restrict__ outp)
{
    int n = blockIdx.x;
    int t = threadIdx.x;
    size_t base = (size_t)n * CT * CD + t * 4;
    float4 a = *(const float4*)(x + base);
    float s  = a.x + a.y + a.z + a.w;
    float ss = a.x * a.x + a.y * a.y + a.z * a.z + a.w * a.w;
#pragma unroll
    for (int o = 16; o > 0; o >>= 1) {
        s  += __shfl_xor_sync(0xffffffffu, s,  o);
        ss += __shfl_xor_sync(0xffffffffu, ss, o);
    }
    __shared__ float sh[18];
    int w = t >> 5;
    if ((t & 31) == 0) { sh[w] = s; sh[8 + w] = ss; }
    __syncthreads();
    if (t == 0) {
        float S = 0.f, SS = 0.f;
        for (int i = 0; i < 8; i++) { S += sh[i]; SS += sh[8 + i]; }
        float m = S * (1.f / CD);
        sh[16] = m;
        sh[17] = rsqrtf(SS * (1.f / CD) - m * m + 1e-5f);
    }
    __syncthreads();
    float m = sh[16], inv = sh[17];
    float4 gg = *(const float4*)(g + t * 4);
    float4 bb = *(const float4*)(b + t * 4);
    float4 o;
    o.x = (a.x - m) * inv * gg.x + bb.x;
    o.y = (a.y - m) * inv * gg.y + bb.y;
    o.z = (a.z - m) * inv * gg.z + bb.z;
    o.w = (a.w - m) * inv * gg.w + bb.w;
    *(float4*)(outp + (size_t)n * CD + t * 4) = o;
}

// ---------------- output head: out[n,c] = cls[n,:] @ Wout[:,c] + bout[c] ----------------
__global__ __launch_bounds__(256) void out_kernel(const float* __restrict__ xc, const float* __restrict__ Wout,
                                                  const float* __restrict__ bout, float* __restrict__ out)
{
    int c = blockIdx.x * 256 + threadIdx.x;
    __shared__ float sx[CB][CD];
    for (int i = threadIdx.x; i < CB * CD; i += 256)
        sx[i >> 10][i & 1023] = xc[i];
    __syncthreads();
    float acc[CB];
#pragma unroll
    for (int n = 0; n < CB; n++) acc[n] = bout[c];
    for (int d = 0; d < CD; d++) {
        float wv = Wout[(size_t)d * CV + c];
#pragma unroll
        for (int n = 0; n < CB; n++) acc[n] += sx[n][d] * wv;
    }
#pragma unroll
    for (int n = 0; n < CB; n++) out[(size_t)n * CV + c] = acc[n];
}

// ---------------- host ----------------
extern "C" void kernel_launch(void* const* d_in, const int* in_sizes, int n_in,
                              void* d_out, int out_size)
{
    (void)in_sizes; (void)n_in; (void)out_size;
    const float* inputs = (const float*)d_in[0];
    const float* We   = (const float*)d_in[1];
    const float* be   = (const float*)d_in[2];
    const float* pos  = (const float*)d_in[3];
    const float* Wq   = (const float*)d_in[4];
    const float* bq   = (const float*)d_in[5];
    const float* Wk   = (const float*)d_in[6];
    const float* bk   = (const float*)d_in[7];
    const float* Wv   = (const float*)d_in[8];
    const float* bv   = (const float*)d_in[9];
    const float* Wo   = (const float*)d_in[10];
    const float* bo   = (const float*)d_in[11];
    const float* ln1g = (const float*)d_in[12];
    const float* ln1b = (const float*)d_in[13];
    const float* W1   = (const float*)d_in[14];
    const float* b1   = (const float*)d_in[15];
    const float* W2   = (const float*)d_in[16];
    const float* b2   = (const float*)d_in[17];
    const float* ln2g = (const float*)d_in[18];
    const float* ln2b = (const float*)d_in[19];
    const float* gN   = (const float*)d_in[20];
    const float* bN   = (const float*)d_in[21];
    const float* Wout = (const float*)d_in[22];
    const float* bout = (const float*)d_in[23];
    float* out = (float*)d_out;

    float *x, *q, *k, *v, *tmp, *ff, *kvp, *ksp, *kv, *ksum, *clsb;
    cudaGetSymbolAddress((void**)&x,    g_x);
    cudaGetSymbolAddress((void**)&q,    g_q);
    cudaGetSymbolAddress((void**)&k,    g_k);
    cudaGetSymbolAddress((void**)&v,    g_v);
    cudaGetSymbolAddress((void**)&tmp,  g_tmp);
    cudaGetSymbolAddress((void**)&ff,   g_ff);
    cudaGetSymbolAddress((void**)&kvp,  g_kvp);
    cudaGetSymbolAddress((void**)&ksp,  g_ksp);
    cudaGetSymbolAddress((void**)&kv,   g_kv);
    cudaGetSymbolAddress((void**)&ksum, g_ksum);
    cudaGetSymbolAddress((void**)&clsb, g_cls);

    // Embedding: x[n, s+1, :] = inputs[n,s,:] @ We + be + pos[s+1]
    {
        dim3 grid(CD / 128, (CB * CSEQ + 127) / 128);
        sgemm<2><<<grid, 256>>>(inputs, We, be, pos, x, CB * CSEQ, CD, CV);
    }
    // CLS rows
    cls_kernel<<<(CB * CD + 255) / 256, 256>>>(We, be, pos, x);

    const int M = CM;
    dim3 gDD(CD / 128, (M + 127) / 128);
    dim3 gDF(CFF / 128, (M + 127) / 128);

    for (int l = 0; l < CNL; l++) {
        const float* Wql = Wq + (size_t)l * CD * CD;
        const float* Wkl = Wk + (size_t)l * CD * CD;
        const float* Wvl = Wv + (size_t)l * CD * CD;
        const float* Wol = Wo + (size_t)l * CD * CD;
        const float* W1l = W1 + (size_t)l * CD * CFF;
        const float* W2l = W2 + (size_t)l * CFF * CD;

        sgemm<0><<<gDD, 256>>>(x, Wql, bq + (size_t)l * CD, nullptr, q, M, CD, CD);
        sgemm<0><<<gDD, 256>>>(x, Wkl, bk + (size_t)l * CD, nullptr, k, M, CD, CD);
        sgemm<0><<<gDD, 256>>>(x, Wvl, bv + (size_t)l * CD, nullptr, v, M, CD, CD);

        rope_phi_kernel<<<(CB * CT * CH * 32 + 255) / 256, 256>>>(q, k);

        kv_partial<<<dim3(CB * CH, 8), 256>>>(k, v, kvp, ksp);
        kv_reduce<<<(CB * CH * CDH * CDH + CB * CH * CDH + 255) / 256, 256>>>(kvp, ksp, kv, ksum);

        attn_kernel<<<dim3(CB * CH, 8), 256>>>(q, kv, ksum, q);   // in place

        sgemm<0><<<gDD, 256>>>(q, Wol, bo + (size_t)l * CD, nullptr, tmp, M, CD, CD);
        ln_kernel<<<M, 256>>>(x, tmp, ln1g + (size_t)l * CD, ln1b + (size_t)l * CD);

        sgemm<1><<<gDF, 256>>>(x, W1l, b1 + (size_t)l * CFF, nullptr, ff, M, CFF, CD);
        sgemm<0><<<gDD, 256>>>(ff, W2l, b2 + (size_t)l * CD, nullptr, tmp, M, CD, CFF);
        ln_kernel<<<M, 256>>>(x, tmp, ln2g + (size_t)l * CD, ln2b + (size_t)l * CD);
    }

    ln_cls_kernel<<<CB, 256>>>(x, gN, bN, clsb);
    out_kernel<<<CV / 256, 256>>>(clsb, Wout, bout, out);
}

// round 6
// speedup vs baseline: 1.0009x; 1.0009x over previous
#include <cuda_runtime.h>
#include <math.h>
#include <stdint.h>

// Problem constants
#define CB   8          // batch
#define CSEQ 2048
#define CT   2049       // SEQ + CLS
#define CV   4096       // vocab
#define CD   1024       // model dim
#define CH   16         // heads
#define CDH  64         // head dim
#define CNL  8          // layers
#define CFF  4096       // ff dim
#define CM   (CB*CT)    // 16392 rows

// ---------------- scratch (device globals; no allocation allowed) ----------------
__device__ float g_x  [(size_t)CB*CT*CD];
__device__ float g_q  [(size_t)CB*CT*CD];
__device__ float g_k  [(size_t)CB*CT*CD];
__device__ float g_v  [(size_t)CB*CT*CD];
__device__ float g_tmp[(size_t)CB*CT*CD];
__device__ float g_ff [(size_t)CB*CT*CFF];
__device__ float g_kvp [(size_t)CB*CH*8*CDH*CDH];   // partial KV per seq-chunk
__device__ float g_ksp [(size_t)CB*CH*8*CDH];       // partial Ksum per seq-chunk
__device__ float g_kv  [(size_t)CB*CH*CDH*CDH];
__device__ float g_ksum[(size_t)CB*CH*CDH];
__device__ float g_cls [(size_t)CB*CD];

// ---------------- helpers ----------------
__device__ __forceinline__ float geluf(float v) {
    return 0.5f * v * (1.0f + erff(v * 0.70710678118654752f));
}

// ---------------- tiled SGEMM: C[M,N] = A[M,K] @ B[K,N] (+epilogue) ----------------
// EPI: 0 = +bias ; 1 = gelu(.+bias) ; 2 = embedding (+bias +pos, remap rows n*2049+s+1)
template<int EPI>
__global__ __launch_bounds__(256, 2) void sgemm(
    const float* __restrict__ A, const float* __restrict__ Bm,
    const float* __restrict__ bias, const float* __restrict__ pos,
    float* __restrict__ C, int M, int N, int K)
{
    __shared__ float As[8][128];
    __shared__ float Bs[8][128];
    const int t = threadIdx.x;
    const int rowBase = blockIdx.y * 128;
    const int colBase = blockIdx.x * 128;
    const int aRow = t >> 1;
    const int aCol = (t & 1) << 2;
    const int bRow = t >> 5;
    const int bCol = (t & 31) << 2;
    const int tx = t & 15, ty = t >> 4;

    float acc[8][8];
#pragma unroll
    for (int i = 0; i < 8; i++)
#pragma unroll
        for (int j = 0; j < 8; j++) acc[i][j] = 0.f;

    const bool aValid = (rowBase + aRow) < M;
    const float* Ap = A + (size_t)(rowBase + aRow) * K + aCol;
    const float* Bp = Bm + (size_t)bRow * N + colBase + bCol;

    for (int k0 = 0; k0 < K; k0 += 8) {
        float4 av = aValid ? *(const float4*)(Ap + k0) : make_float4(0.f, 0.f, 0.f, 0.f);
        As[aCol + 0][aRow] = av.x;
        As[aCol + 1][aRow] = av.y;
        As[aCol + 2][aRow] = av.z;
        As[aCol + 3][aRow] = av.w;
        *(float4*)&Bs[bRow][bCol] = *(const float4*)(Bp + (size_t)k0 * N);
        __syncthreads();
#pragma unroll
        for (int k = 0; k < 8; k++) {
            float ra[8], rb[8];
            *(float4*)&ra[0] = *(const float4*)&As[k][ty * 4];
            *(float4*)&ra[4] = *(const float4*)&As[k][ty * 4 + 64];
            *(float4*)&rb[0] = *(const float4*)&Bs[k][tx * 4];
            *(float4*)&rb[4] = *(const float4*)&Bs[k][tx * 4 + 64];
#pragma unroll
            for (int i = 0; i < 8; i++)
#pragma unroll
                for (int j = 0; j < 8; j++) acc[i][j] += ra[i] * rb[j];
        }
        __syncthreads();
    }

#pragma unroll
    for (int i = 0; i < 8; i++) {
        int r = rowBase + ty * 4 + ((i < 4) ? i : 64 + i - 4);
        if (r >= M) continue;
        size_t outRow = (size_t)r;
        const float* posRow = nullptr;
        if (EPI == 2) {
            int n = r >> 11;        // / 2048
            int s = r & 2047;
            outRow = (size_t)n * CT + s + 1;
            posRow = pos + (size_t)(s + 1) * CD;
        }
#pragma unroll
        for (int jh = 0; jh < 2; jh++) {
            int c = colBase + tx * 4 + jh * 64;
            float4 v;
            v.x = acc[i][jh * 4 + 0] + bias[c + 0];
            v.y = acc[i][jh * 4 + 1] + bias[c + 1];
            v.z = acc[i][jh * 4 + 2] + bias[c + 2];
            v.w = acc[i][jh * 4 + 3] + bias[c + 3];
            if (EPI == 1) { v.x = geluf(v.x); v.y = geluf(v.y); v.z = geluf(v.z); v.w = geluf(v.w); }
            if (EPI == 2) { v.x += posRow[c + 0]; v.y += posRow[c + 1]; v.z += posRow[c + 2]; v.w += posRow[c + 3]; }
            *(float4*)&C[outRow * N + c] = v;
        }
    }
}

// ---------------- CLS row: x[n,0,:] = We[V-1,:] + be + pos[0,:] ----------------
__global__ void cls_kernel(const float* __restrict__ We, const float* __restrict__ be,
                           const float* __restrict__ pos, float* __restrict__ x)
{
    int idx = blockIdx.x * 256 + threadIdx.x;
    if (idx >= CB * CD) return;
    int n = idx >> 10, c = idx & 1023;
    x[(size_t)n * CT * CD + c] = We[(size_t)(CV - 1) * CD + c] + be[c] + pos[c];
}

// ---------------- RoPE + phi(x)=elu(x)+1 on q and k, in place ----------------
__global__ void rope_phi_kernel(float* __restrict__ q, float* __restrict__ k)
{
    int idx = blockIdx.x * 256 + threadIdx.x;           // over B*T*H*32
    if (idx >= CB * CT * CH * 32) return;
    int j  = idx & 31;
    int h  = (idx >> 5) & 15;
    int nt = idx >> 9;                                  // n*T + t
    int tt = nt % CT;
    int n  = nt / CT;
    size_t base = (((size_t)n * CT + tt) * CH + h) * CDH;
    float invf = 1.0f / powf(10000.0f, (float)(2 * j) / (float)CDH);
    float ang = (float)tt * invf;
    float c, s;
    sincosf(ang, &s, &c);

    float q1 = q[base + j], q2 = q[base + j + 32];
    float qa = q1 * c - q2 * s;
    float qb = q2 * c + q1 * s;
    q[base + j]      = (qa > 0.f) ? (qa + 1.f) : expf(qa);
    q[base + j + 32] = (qb > 0.f) ? (qb + 1.f) : expf(qb);

    float k1 = k[base + j], k2 = k[base + j + 32];
    float ka = k1 * c - k2 * s;
    float kb = k2 * c + k1 * s;
    k[base + j]      = (ka > 0.f) ? (ka + 1.f) : expf(ka);
    k[base + j + 32] = (kb > 0.f) ? (kb + 1.f) : expf(kb);
}

// ---------------- KV partial: per (n,h,chunk): KV += Kf^T @ V over seq chunk ----------------
__global__ __launch_bounds__(256) void kv_partial(const float* __restrict__ Kf, const float* __restrict__ Vf,
                                                  float* __restrict__ kvp, float* __restrict__ ksp)
{
    int nh = blockIdx.x, ch = blockIdx.y;
    int n = nh >> 4, h = nh & 15;
    int s0 = ch * 257;
    int s1 = min(s0 + 257, CT);
    int t = threadIdx.x;
    int d0 = t >> 2;
    int mq = (t & 3) << 4;
    __shared__ float sk[8][64];
    __shared__ float sv[8][64];
    float acc[16];
#pragma unroll
    for (int j = 0; j < 16; j++) acc[j] = 0.f;
    float ks = 0.f;

    for (int s = s0; s < s1; s += 8) {
        int nr = min(8, s1 - s);
        for (int i = t; i < nr * 64; i += 256) {
            int rr = i >> 6, dd = i & 63;
            size_t off = (((size_t)n * CT + (s + rr)) * CH + h) * CDH + dd;
            sk[rr][dd] = Kf[off];
            sv[rr][dd] = Vf[off];
        }
        __syncthreads();
        for (int rr = 0; rr < nr; rr++) {
            float kd = sk[rr][d0];
            ks += kd;
            const float4* v4 = (const float4*)&sv[rr][mq];
            float4 v0 = v4[0], v1 = v4[1], v2 = v4[2], v3 = v4[3];
            acc[0]  += kd * v0.x;  acc[1]  += kd * v0.y;  acc[2]  += kd * v0.z;  acc[3]  += kd * v0.w;
            acc[4]  += kd * v1.x;  acc[5]  += kd * v1.y;  acc[6]  += kd * v1.z;  acc[7]  += kd * v1.w;
            acc[8]  += kd * v2.x;  acc[9]  += kd * v2.y;  acc[10] += kd * v2.z;  acc[11] += kd * v2.w;
            acc[12] += kd * v3.x;  acc[13] += kd * v3.y;  acc[14] += kd * v3.z;  acc[15] += kd * v3.w;
        }
        __syncthreads();
    }
    size_t ob = ((size_t)nh * 8 + ch) * (CDH * CDH) + (size_t)d0 * CDH + mq;
#pragma unroll
    for (int j = 0; j < 16; j++) kvp[ob + j] = acc[j];
    if ((t & 3) == 0) ksp[((size_t)nh * 8 + ch) * CDH + d0] = ks;
}

// ---------------- deterministic reduce of the 8 chunks ----------------
__global__ void kv_reduce(const float* __restrict__ kvp, const float* __restrict__ ksp,
                          float* __restrict__ kv, float* __restrict__ ksum)
{
    int idx = blockIdx.x * 256 + threadIdx.x;
    const int NKV = CB * CH * CDH * CDH;
    if (idx < NKV) {
        int nh = idx >> 12, r = idx & 4095;
        float s = 0.f;
        for (int c = 0; c < 8; c++) s += kvp[((size_t)nh * 8 + c) * (CDH * CDH) + r];
        kv[idx] = s;
    } else if (idx < NKV + CB * CH * CDH) {
        int i2 = idx - NKV;
        int nh = i2 >> 6, r = i2 & 63;
        float s = 0.f;
        for (int c = 0; c < 8; c++) s += ksp[((size_t)nh * 8 + c) * CDH + r];
        ksum[i2] = s;
    }
}

// ---------------- attn: out[t,m] = (Qf[t,:] @ KV[:,m]) / (Qf[t,:]·Ksum + eps) ----------------
__global__ __launch_bounds__(256) void attn_kernel(const float* __restrict__ Qf, const float* __restrict__ kv,
                                                   const float* __restrict__ ksum, float* __restrict__ out)
{
    int nh = blockIdx.x, ch = blockIdx.y;
    int n = nh >> 4, h = nh & 15;
    int t = threadIdx.x;
    __shared__ float skvt[64][68];   // transposed, padded: skvt[m][d] = KV[d][m]
    __shared__ float sks[64];
    __shared__ float sq[4][64];
    for (int i = t; i < 4096; i += 256) {
        int d = i >> 6, m = i & 63;
        skvt[m][d] = kv[(size_t)nh * 4096 + i];
    }
    if (t < 64) sks[t] = ksum[(size_t)nh * 64 + t];
    __syncthreads();

    int g = t >> 6, m = t & 63;
    int s0 = ch * 257;
    int s1 = min(s0 + 257, CT);
    for (int tt = s0; tt < s1; tt += 4) {
        int nr = min(4, s1 - tt);
        if (t < nr * 64)
            sq[t >> 6][t & 63] = Qf[(((size_t)n * CT + (tt + (t >> 6))) * CH + h) * CDH + (t & 63)];
        __syncthreads();
        if (g < nr) {
            float sm = 0.f, sz = 0.f;
#pragma unroll
            for (int d = 0; d < 64; d += 4) {
                float4 q4 = *(const float4*)&sq[g][d];
                float4 k4 = *(const float4*)&skvt[m][d];
                float4 z4 = *(const float4*)&sks[d];
                sm += q4.x * k4.x + q4.y * k4.y + q4.z * k4.z + q4.w * k4.w;
                sz += q4.x * z4.x + q4.y * z4.y + q4.z * z4.z + q4.w * z4.w;
            }
            out[(((size_t)n * CT + (tt + g)) * CH + h) * CDH + m] = sm / (sz + 1e-6f);
        }
        __syncthreads();
    }
}

// ---------------- fused residual + LayerNorm (in place on x) ----------------
__global__ __launch_bounds__(256) void ln_kernel(float* __restrict__ x, const float* __restrict__ res,
                                                 const float* __restrict__ g, const float* __restrict__ b)
{
    int row = blockIdx.x;
    int t = threadIdx.x;
    size_t base = (size_t)row * CD + t * 4;
    float4 a = *(const float4*)(x + base);
    float4 r = *(const float4*)(res + base);
    a.x += r.x; a.y += r.y; a.z += r.z; a.w += r.w;
    float s  = a.x + a.y + a.z + a.w;
    float ss = a.x * a.x + a.y * a.y + a.z * a.z + a.w * a.w;
#pragma unroll
    for (int o = 16; o > 0; o >>= 1) {
        s  += __shfl_xor_sync(0xffffffffu, s,  o);
        ss += __shfl_xor_sync(0xffffffffu, ss, o);
    }
    __shared__ float sh[18];
    int w = t >> 5;
    if ((t & 31) == 0) { sh[w] = s; sh[8 + w] = ss; }
    __syncthreads();
    if (t == 0) {
        float S = 0.f, SS = 0.f;
        for (int i = 0; i < 8; i++) { S += sh[i]; SS += sh[8 + i]; }
        float m = S * (1.f / CD);
        sh[16] = m;
        sh[17] = rsqrtf(SS * (1.f / CD) - m * m + 1e-5f);
    }
    __syncthreads();
    float m = sh[16], inv = sh[17];
    float4 gg = *(const float4*)(g + t * 4);
    float4 bb = *(const float4*)(b + t * 4);
    float4 o;
    o.x = (a.x - m) * inv * gg.x + bb.x;
    o.y = (a.y - m) * inv * gg.y + bb.y;
    o.z = (a.z - m) * inv * gg.z + bb.z;
    o.w = (a.w - m) * inv * gg.w + bb.w;
    *(float4*)(x + base) = o;
}

// ---------------- final LN on the 8 CLS rows ----------------
__global__ __launch_bounds__(256) void ln_cls_kernel(const float* __restrict__ x, const float* __restrict__ g,
                                                     const float* __restrict__ b, float* __restrict__ outp)
{
    int n = blockIdx.x;
    int t = threadIdx.x;
    size_t base = (size_t)n * CT * CD + t * 4;
    float4 a = *(const float4*)(x + base);
    float s  = a.x + a.y + a.z + a.w;
    float ss = a.x * a.x + a.y * a.y + a.z * a.z + a.w * a.w;
#pragma unroll
    for (int o = 16; o > 0; o >>= 1) {
        s  += __shfl_xor_sync(0xffffffffu, s,  o);
        ss += __shfl_xor_sync(0xffffffffu, ss, o);
    }
    __shared__ float sh[18];
    int w = t >> 5;
    if ((t & 31) == 0) { sh[w] = s; sh[8 + w] = ss; }
    __syncthreads();
    if (t == 0) {
        float S = 0.f, SS = 0.f;
        for (int i = 0; i < 8; i++) { S += sh[i]; SS += sh[8 + i]; }
        float m = S * (1.f / CD);
        sh[16] = m;
        sh[17] = rsqrtf(SS * (1.f / CD) - m * m + 1e-5f);
    }
    __syncthreads();
    float m = sh[16], inv = sh[17];
    float4 gg = *(const float4*)(g + t * 4);
    float4 bb = *(const float4*)(b + t * 4);
    float4 o;
    o.x = (a.x - m) * inv * gg.x + bb.x;
    o.y = (a.y - m) * inv * gg.y + bb.y;
    o.z = (a.z - m) * inv * gg.z + bb.z;
    o.w = (a.w - m) * inv * gg.w + bb.w;
    *(float4*)(outp + (size_t)n * CD + t * 4) = o;
}

// ---------------- output head: out[n,c] = cls[n,:] @ Wout[:,c] + bout[c] ----------------
__global__ __launch_bounds__(256) void out_kernel(const float* __restrict__ xc, const float* __restrict__ Wout,
                                                  const float* __restrict__ bout, float* __restrict__ out)
{
    int c = blockIdx.x * 256 + threadIdx.x;
    __shared__ float sx[CB][CD];
    for (int i = threadIdx.x; i < CB * CD; i += 256)
        sx[i >> 10][i & 1023] = xc[i];
    __syncthreads();
    float acc[CB];
#pragma unroll
    for (int n = 0; n < CB; n++) acc[n] = bout[c];
    for (int d = 0; d < CD; d++) {
        float wv = Wout[(size_t)d * CV + c];
#pragma unroll
        for (int n = 0; n < CB; n++) acc[n] += sx[n][d] * wv;
    }
#pragma unroll
    for (int n = 0; n < CB; n++) out[(size_t)n * CV + c] = acc[n];
}

// ---------------- host ----------------
extern "C" void kernel_launch(void* const* d_in, const int* in_sizes, int n_in,
                              void* d_out, int out_size)
{
    (void)in_sizes; (void)n_in; (void)out_size;
    const float* inputs = (const float*)d_in[0];
    const float* We   = (const float*)d_in[1];
    const float* be   = (const float*)d_in[2];
    const float* pos  = (const float*)d_in[3];
    const float* Wq   = (const float*)d_in[4];
    const float* bq   = (const float*)d_in[5];
    const float* Wk   = (const float*)d_in[6];
    const float* bk   = (const float*)d_in[7];
    const float* Wv   = (const float*)d_in[8];
    const float* bv   = (const float*)d_in[9];
    const float* Wo   = (const float*)d_in[10];
    const float* bo   = (const float*)d_in[11];
    const float* ln1g = (const float*)d_in[12];
    const float* ln1b = (const float*)d_in[13];
    const float* W1   = (const float*)d_in[14];
    const float* b1   = (const float*)d_in[15];
    const float* W2   = (const float*)d_in[16];
    const float* b2   = (const float*)d_in[17];
    const float* ln2g = (const float*)d_in[18];
    const float* ln2b = (const float*)d_in[19];
    const float* gN   = (const float*)d_in[20];
    const float* bN   = (const float*)d_in[21];
    const float* Wout = (const float*)d_in[22];
    const float* bout = (const float*)d_in[23];
    float* out = (float*)d_out;

    float *x, *q, *k, *v, *tmp, *ff, *kvp, *ksp, *kv, *ksum, *clsb;
    cudaGetSymbolAddress((void**)&x,    g_x);
    cudaGetSymbolAddress((void**)&q,    g_q);
    cudaGetSymbolAddress((void**)&k,    g_k);
    cudaGetSymbolAddress((void**)&v,    g_v);
    cudaGetSymbolAddress((void**)&tmp,  g_tmp);
    cudaGetSymbolAddress((void**)&ff,   g_ff);
    cudaGetSymbolAddress((void**)&kvp,  g_kvp);
    cudaGetSymbolAddress((void**)&ksp,  g_ksp);
    cudaGetSymbolAddress((void**)&kv,   g_kv);
    cudaGetSymbolAddress((void**)&ksum, g_ksum);
    cudaGetSymbolAddress((void**)&clsb, g_cls);

    // Embedding: x[n, s+1, :] = inputs[n,s,:] @ We + be + pos[s+1]
    {
        dim3 grid(CD / 128, (CB * CSEQ + 127) / 128);
        sgemm<2><<<grid, 256>>>(inputs, We, be, pos, x, CB * CSEQ, CD, CV);
    }
    // CLS rows
    cls_kernel<<<(CB * CD + 255) / 256, 256>>>(We, be, pos, x);

    const int M = CM;
    dim3 gDD(CD / 128, (M + 127) / 128);
    dim3 gDF(CFF / 128, (M + 127) / 128);

    for (int l = 0; l < CNL; l++) {
        const float* Wql = Wq + (size_t)l * CD * CD;
        const float* Wkl = Wk + (size_t)l * CD * CD;
        const float* Wvl = Wv + (size_t)l * CD * CD;
        const float* Wol = Wo + (size_t)l * CD * CD;
        const float* W1l = W1 + (size_t)l * CD * CFF;
        const float* W2l = W2 + (size_t)l * CFF * CD;

        sgemm<0><<<gDD, 256>>>(x, Wql, bq + (size_t)l * CD, nullptr, q, M, CD, CD);
        sgemm<0><<<gDD, 256>>>(x, Wkl, bk + (size_t)l * CD, nullptr, k, M, CD, CD);
        sgemm<0><<<gDD, 256>>>(x, Wvl, bv + (size_t)l * CD, nullptr, v, M, CD, CD);

        rope_phi_kernel<<<(CB * CT * CH * 32 + 255) / 256, 256>>>(q, k);

        kv_partial<<<dim3(CB * CH, 8), 256>>>(k, v, kvp, ksp);
        kv_reduce<<<(CB * CH * CDH * CDH + CB * CH * CDH + 255) / 256, 256>>>(kvp, ksp, kv, ksum);

        attn_kernel<<<dim3(CB * CH, 8), 256>>>(q, kv, ksum, q);   // in place

        sgemm<0><<<gDD, 256>>>(q, Wol, bo + (size_t)l * CD, nullptr, tmp, M, CD, CD);
        ln_kernel<<<M, 256>>>(x, tmp, ln1g + (size_t)l * CD, ln1b + (size_t)l * CD);

        sgemm<1><<<gDF, 256>>>(x, W1l, b1 + (size_t)l * CFF, nullptr, ff, M, CFF, CD);
        sgemm<0><<<gDD, 256>>>(ff, W2l, b2 + (size_t)l * CD, nullptr, tmp, M, CD, CFF);
        ln_kernel<<<M, 256>>>(x, tmp, ln2g + (size_t)l * CD, ln2b + (size_t)l * CD);
    }

    ln_cls_kernel<<<CB, 256>>>(x, gN, bN, clsb);
    out_kernel<<<CV / 256, 256>>>(clsb, Wout, bout, out);
}

// round 12
// speedup vs baseline: 2.2321x; 2.2301x over previous
#include <cuda_runtime.h>
#include <cuda_bf16.h>
#include <math.h>
#include <stdint.h>

#define CB 8
#define CSEQ 2048
#define CT 2049
#define CV 4096
#define CD 1024
#define CH 16
#define CDH 64
#define CNL 8
#define CFF 4096
#define CM (CB*CT)
#define MPAD 16512

__device__ __forceinline__ uint32_t smem_u32(const void* p) {
    uint32_t a;
    asm("{ .reg .u64 t; cvta.to.shared.u64 t, %1; cvt.u32.u64 %0, t; }" : "=r"(a) : "l"(p));
    return a;
}

#define CP_COMMIT() asm volatile("cp.async.commit_group;" ::: "memory")
#define CP_WAIT1()  asm volatile("cp.async.wait_group 1;" ::: "memory")
#define CP_WAIT0()  asm volatile("cp.async.wait_group 0;" ::: "memory")

__device__ __forceinline__ void ldgsts(uint32_t dst, const void* src, uint32_t srcsize) {
    asm volatile("cp.async.cg.shared.global [%0], [%1], 16, %2;"
        :: "r"(dst), "l"(src), "r"(srcsize) : "memory");
}
__device__ __forceinline__ void ldm4(uint32_t* r, uint32_t addr) {
    asm volatile("ldmatrix.sync.aligned.m8n8.x4.shared.b16 {%0,%1,%2,%3}, [%4];"
        : "=r"(r[0]), "=r"(r[1]), "=r"(r[2]), "=r"(r[3]) : "r"(addr));
}
__device__ __forceinline__ void mma16816(float* c, const uint32_t* a, uint32_t b0, uint32_t b1) {
    asm volatile("mma.sync.aligned.m16n8k16.row.col.f32.bf16.bf16.f32 "
        "{%0,%1,%2,%3}, {%4,%5,%6,%7}, {%8,%9}, {%0,%1,%2,%3};"
        : "+f"(c[0]), "+f"(c[1]), "+f"(c[2]), "+f"(c[3])
        : "r"(a[0]), "r"(a[1]), "r"(a[2]), "r"(a[3]), "r"(b0), "r"(b1));
}

// transposed-split weights: WeT then per layer {q,k,v,o,w1t,w2t}
#define W_TOTAL 104857600ull
#define W_WE    0ull
#define W_L(l)  (4194304ull + (unsigned long long)(l)*12582912ull)
#define W_Q(l)  (W_L(l))
#define W_K(l)  (W_L(l) + 1048576ull)
#define W_V(l)  (W_L(l) + 2097152ull)
#define W_O(l)  (W_L(l) + 3145728ull)
#define W_W1(l) (W_L(l) + 4194304ull)
#define W_W2(l) (W_L(l) + 8388608ull)

__device__ __align__(16) __nv_bfloat16 g_wh[W_TOTAL];
__device__ __align__(16) __nv_bfloat16 g_wl[W_TOTAL];
__device__ __align__(16) __nv_bfloat16 g_sxh[(size_t)MPAD*CD];
__device__ __align__(16) __nv_bfloat16 g_sxl[(size_t)MPAD*CD];
__device__ __align__(16) __nv_bfloat16 g_axh[(size_t)MPAD*CD];
__device__ __align__(16) __nv_bfloat16 g_axl[(size_t)MPAD*CD];
__device__ __align__(16) __nv_bfloat16 g_sfh[(size_t)MPAD*CFF];
__device__ __align__(16) __nv_bfloat16 g_sfl[(size_t)MPAD*CFF];
__device__ float g_x  [(size_t)CM*CD];
__device__ float g_q  [(size_t)CM*CD];
__device__ float g_k  [(size_t)CM*CD];
__device__ float g_v  [(size_t)CM*CD];
__device__ float g_tmp[(size_t)CM*CD];
__device__ float g_kvp [(size_t)CB*CH*8*CDH*CDH];
__device__ float g_ksp [(size_t)CB*CH*8*CDH];
__device__ float g_kv  [(size_t)CB*CH*CDH*CDH];
__device__ float g_ksum[(size_t)CB*CH*CDH];
__device__ float g_cls [(size_t)CB*CD];

__device__ __forceinline__ float geluf(float v) {
    return 0.5f * v * (1.0f + erff(v * 0.70710678118654752f));
}
__device__ __forceinline__ void split_store4(float4 v, __nv_bfloat16* ph, __nv_bfloat16* pl) {
    __nv_bfloat16 hx = __float2bfloat16(v.x), hy = __float2bfloat16(v.y);
    __nv_bfloat16 hz = __float2bfloat16(v.z), hw = __float2bfloat16(v.w);
    __nv_bfloat162 h0; h0.x = hx; h0.y = hy;
    __nv_bfloat162 h1; h1.x = hz; h1.y = hw;
    ((__nv_bfloat162*)ph)[0] = h0; ((__nv_bfloat162*)ph)[1] = h1;
    __nv_bfloat162 l0, l1;
    l0.x = __float2bfloat16(v.x - __bfloat162float(hx));
    l0.y = __float2bfloat16(v.y - __bfloat162float(hy));
    l1.x = __float2bfloat16(v.z - __bfloat162float(hz));
    l1.y = __float2bfloat16(v.w - __bfloat162float(hw));
    ((__nv_bfloat162*)pl)[0] = l0; ((__nv_bfloat162*)pl)[1] = l1;
}
__device__ __forceinline__ void split_store2(float v0, float v1, __nv_bfloat16* ph, __nv_bfloat16* pl) {
    __nv_bfloat16 h0 = __float2bfloat16(v0), h1 = __float2bfloat16(v1);
    __nv_bfloat162 H; H.x = h0; H.y = h1;
    *(__nv_bfloat162*)ph = H;
    __nv_bfloat162 L;
    L.x = __float2bfloat16(v0 - __bfloat162float(h0));
    L.y = __float2bfloat16(v1 - __bfloat162float(h1));
    *(__nv_bfloat162*)pl = L;
}
__device__ __forceinline__ void split_store1(float v, __nv_bfloat16* ph, __nv_bfloat16* pl) {
    __nv_bfloat16 h = __float2bfloat16(v);
    *ph = h;
    *pl = __float2bfloat16(v - __bfloat162float(h));
}

// W[K,N] fp32 -> T[N,K] bf16 hi/lo
__global__ __launch_bounds__(256) void split_w(const float* __restrict__ W,
                                               __nv_bfloat16* __restrict__ Th,
                                               __nv_bfloat16* __restrict__ Tl, int K, int N)
{
    __shared__ float tile[32][33];
    int kb = blockIdx.y * 32, nb = blockIdx.x * 32;
    int tx = threadIdx.x & 31, ty = threadIdx.x >> 5;
    for (int i = ty; i < 32; i += 8)
        tile[i][tx] = W[(size_t)(kb + i) * N + nb + tx];
    __syncthreads();
    for (int i = ty; i < 32; i += 8) {
        float v = tile[tx][i];
        size_t o = (size_t)(nb + i) * K + kb + tx;
        __nv_bfloat16 h = __float2bfloat16(v);
        Th[o] = h;
        Tl[o] = __float2bfloat16(v - __bfloat162float(h));
    }
}

__global__ void split_in(const float* __restrict__ in, __nv_bfloat16* __restrict__ oh,
                         __nv_bfloat16* __restrict__ ol)
{
    size_t i4 = (size_t)blockIdx.x * 256 + threadIdx.x;
    if (i4 >= (size_t)16384 * 4096 / 4) return;
    float4 v = *(const float4*)(in + i4 * 4);
    split_store4(v, oh + i4 * 4, ol + i4 * 4);
}

// ---------------- mma.sync split-bf16 GEMM: C[M,N] = A[M,K] @ B[N,K]^T ----------------
// SMEM per stage: Ah(16K) Al(16K) Bh(16K) Bl(16K); 2 stages = 128KB dynamic.
#define TG_SMEM 131072
template<int EPI>
__global__ __launch_bounds__(256, 1) void tgemm(
    const __nv_bfloat16* __restrict__ Ah, const __nv_bfloat16* __restrict__ Al,
    const __nv_bfloat16* __restrict__ Bh, const __nv_bfloat16* __restrict__ Bl,
    const float* __restrict__ bias, const float* __restrict__ pos,
    float* __restrict__ outf, __nv_bfloat16* __restrict__ outh, __nv_bfloat16* __restrict__ outl,
    int M, int N, int K)
{
    extern __shared__ char smem[];
    const uint32_t sbase = smem_u32(smem);
    const int tid = threadIdx.x;
    const int lane = tid & 31, wid = tid >> 5;
    const int wm = wid >> 2, wn = wid & 3;           // warp grid 2(M) x 4(N)
    const int rowBase = blockIdx.y * 128;
    const int colBase = blockIdx.x * 128;
    const int NK = K >> 6;

    float c[4][4][4];
#pragma unroll
    for (int i = 0; i < 4; i++)
#pragma unroll
        for (int j = 0; j < 4; j++)
#pragma unroll
            for (int p = 0; p < 4; p++) c[i][j][p] = 0.f;

    // global->smem indices: per iter it: row r = it*32 + tid/8, 16B chunk c8 = tid%8
    const int lr8 = tid >> 3;
    const int c8  = tid & 7;

    // ldmatrix addressing
    const int lr = lane & 15;
    const uint32_t xorv = ((uint32_t)(lr & 7)) << 4;
    const int hb = (lane >> 4) << 4;                 // 0 or 16 bytes
    uint32_t aRow[4], bRow[2];
#pragma unroll
    for (int i = 0; i < 4; i++) aRow[i] = (uint32_t)(wm * 64 + i * 16 + lr) * 128;
#pragma unroll
    for (int j = 0; j < 2; j++) bRow[j] = (uint32_t)(wn * 32 + j * 16 + lr) * 128;

    // ---- prologue: load chunk 0 into stage 0 ----
    {
        uint32_t sb = sbase;
        size_t kc = (size_t)c8 * 8;
#pragma unroll
        for (int it = 0; it < 4; it++) {
            int r = it * 32 + lr8;
            uint32_t off = (uint32_t)r * 128 + (((uint32_t)c8 * 16) ^ (((uint32_t)r & 7) << 4));
            int ga = rowBase + r;
            uint32_t szA = (ga < M) ? 16u : 0u;
            size_t ao = (size_t)((ga < M) ? ga : 0) * K + kc;
            ldgsts(sb + off,         Ah + ao, szA);
            ldgsts(sb + 16384 + off, Al + ao, szA);
            size_t bo = (size_t)(colBase + r) * K + kc;
            ldgsts(sb + 32768 + off, Bh + bo, 16u);
            ldgsts(sb + 49152 + off, Bl + bo, 16u);
        }
        CP_COMMIT();
    }

    for (int ch = 0; ch < NK; ch++) {
        if (ch + 1 < NK) {
            uint32_t sb = sbase + ((ch + 1) & 1) * 65536;
            size_t kc = (size_t)(ch + 1) * 64 + c8 * 8;
#pragma unroll
            for (int it = 0; it < 4; it++) {
                int r = it * 32 + lr8;
                uint32_t off = (uint32_t)r * 128 + (((uint32_t)c8 * 16) ^ (((uint32_t)r & 7) << 4));
                int ga = rowBase + r;
                uint32_t szA = (ga < M) ? 16u : 0u;
                size_t ao = (size_t)((ga < M) ? ga : 0) * K + kc;
                ldgsts(sb + off,         Ah + ao, szA);
                ldgsts(sb + 16384 + off, Al + ao, szA);
                size_t bo = (size_t)(colBase + r) * K + kc;
                ldgsts(sb + 32768 + off, Bh + bo, 16u);
                ldgsts(sb + 49152 + off, Bl + bo, 16u);
            }
            CP_COMMIT();
            CP_WAIT1();
        } else {
            CP_WAIT0();
        }
        __syncthreads();

        uint32_t sb = sbase + (ch & 1) * 65536;
#pragma unroll
        for (int kk = 0; kk < 4; kk++) {
            uint32_t cb = ((uint32_t)(kk * 32 + hb)) ^ xorv;
            uint32_t ahf[4][4], alf[4][4], bhf[2][4], blf[2][4];
#pragma unroll
            for (int i = 0; i < 4; i++) {
                uint32_t ad = sb + aRow[i] + cb;
                ldm4(ahf[i], ad);
                ldm4(alf[i], ad + 16384);
            }
#pragma unroll
            for (int j = 0; j < 2; j++) {
                uint32_t bd = sb + 32768 + bRow[j] + cb;
                ldm4(bhf[j], bd);
                ldm4(blf[j], bd + 16384);
            }
#pragma unroll
            for (int mi = 0; mi < 4; mi++) {
#pragma unroll
                for (int nj = 0; nj < 4; nj++) {
                    float* cc = c[mi][nj];
                    int j2 = nj >> 1, od = nj & 1;
                    uint32_t b0h = bhf[j2][od], b1h = bhf[j2][2 + od];
                    mma16816(cc, ahf[mi], b0h, b1h);
                    mma16816(cc, ahf[mi], blf[j2][od], blf[j2][2 + od]);
                    mma16816(cc, alf[mi], b0h, b1h);
                }
            }
        }
        __syncthreads();
    }

    // ---- epilogue: direct global stores ----
    const int cr = lane >> 2;
    const int ccol = (lane & 3) * 2;
#pragma unroll
    for (int mi = 0; mi < 4; mi++) {
#pragma unroll
        for (int half = 0; half < 2; half++) {
            int row = rowBase + wm * 64 + mi * 16 + cr + half * 8;
            if (row >= M) continue;
            size_t orow = (size_t)row;
            const float* prow = nullptr;
            if (EPI == 2) {
                int n = row >> 11, s = row & 2047;
                orow = (size_t)n * CT + s + 1;
                prow = pos + (size_t)(s + 1) * CD;
            }
#pragma unroll
            for (int nj = 0; nj < 4; nj++) {
                int col = colBase + wn * 32 + nj * 8 + ccol;
                float2 bb = *(const float2*)&bias[col];
                float v0 = c[mi][nj][half * 2 + 0] + bb.x;
                float v1 = c[mi][nj][half * 2 + 1] + bb.y;
                if (EPI == 0) {
                    float2 o; o.x = v0; o.y = v1;
                    *(float2*)&outf[orow * N + col] = o;
                } else if (EPI == 1) {
                    v0 = geluf(v0); v1 = geluf(v1);
                    split_store2(v0, v1, outh + orow * N + col, outl + orow * N + col);
                } else {
                    v0 += prow[col]; v1 += prow[col + 1];
                    float2 o; o.x = v0; o.y = v1;
                    *(float2*)&outf[orow * N + col] = o;
                    split_store2(v0, v1, outh + orow * N + col, outl + orow * N + col);
                }
            }
        }
    }
}

// ---------------- CLS row ----------------
__global__ void cls_kernel(const float* __restrict__ We, const float* __restrict__ be,
                           const float* __restrict__ pos, float* __restrict__ x,
                           __nv_bfloat16* __restrict__ xh, __nv_bfloat16* __restrict__ xl)
{
    int idx = blockIdx.x * 256 + threadIdx.x;
    if (idx >= CB * CD) return;
    int n = idx >> 10, c = idx & 1023;
    float v = We[(size_t)(CV - 1) * CD + c] + be[c] + pos[c];
    size_t o = (size_t)n * CT * CD + c;
    x[o] = v;
    split_store1(v, xh + o, xl + o);
}

// ---------------- RoPE + phi ----------------
__global__ void rope_phi_kernel(float* __restrict__ q, float* __restrict__ k)
{
    int idx = blockIdx.x * 256 + threadIdx.x;
    if (idx >= CB * CT * CH * 32) return;
    int j  = idx & 31;
    int h  = (idx >> 5) & 15;
    int nt = idx >> 9;
    int tt = nt % CT;
    int n  = nt / CT;
    size_t base = (((size_t)n * CT + tt) * CH + h) * CDH;
    float invf = 1.0f / powf(10000.0f, (float)(2 * j) / (float)CDH);
    float ang = (float)tt * invf;
    float c, s;
    sincosf(ang, &s, &c);
    float q1 = q[base + j], q2 = q[base + j + 32];
    float qa = q1 * c - q2 * s, qb = q2 * c + q1 * s;
    q[base + j]      = (qa > 0.f) ? (qa + 1.f) : expf(qa);
    q[base + j + 32] = (qb > 0.f) ? (qb + 1.f) : expf(qb);
    float k1 = k[base + j], k2 = k[base + j + 32];
    float ka = k1 * c - k2 * s, kb = k2 * c + k1 * s;
    k[base + j]      = (ka > 0.f) ? (ka + 1.f) : expf(ka);
    k[base + j + 32] = (kb > 0.f) ? (kb + 1.f) : expf(kb);
}

// ---------------- KV partials ----------------
__global__ __launch_bounds__(256) void kv_partial(const float* __restrict__ Kf, const float* __restrict__ Vf,
                                                  float* __restrict__ kvp, float* __restrict__ ksp)
{
    int nh = blockIdx.x, ch = blockIdx.y;
    int n = nh >> 4, h = nh & 15;
    int s0 = ch * 257, s1 = min(s0 + 257, CT);
    int t = threadIdx.x;
    int d0 = t >> 2, mq = (t & 3) << 4;
    __shared__ float sk[8][64];
    __shared__ float sv[8][64];
    float acc[16];
#pragma unroll
    for (int j = 0; j < 16; j++) acc[j] = 0.f;
    float ks = 0.f;
    for (int s = s0; s < s1; s += 8) {
        int nr = min(8, s1 - s);
        for (int i = t; i < nr * 64; i += 256) {
            int rr = i >> 6, dd = i & 63;
            size_t off = (((size_t)n * CT + (s + rr)) * CH + h) * CDH + dd;
            sk[rr][dd] = Kf[off];
            sv[rr][dd] = Vf[off];
        }
        __syncthreads();
        for (int rr = 0; rr < nr; rr++) {
            float kd = sk[rr][d0];
            ks += kd;
            const float4* v4 = (const float4*)&sv[rr][mq];
            float4 v0 = v4[0], v1 = v4[1], v2 = v4[2], v3 = v4[3];
            acc[0]  += kd * v0.x;  acc[1]  += kd * v0.y;  acc[2]  += kd * v0.z;  acc[3]  += kd * v0.w;
            acc[4]  += kd * v1.x;  acc[5]  += kd * v1.y;  acc[6]  += kd * v1.z;  acc[7]  += kd * v1.w;
            acc[8]  += kd * v2.x;  acc[9]  += kd * v2.y;  acc[10] += kd * v2.z;  acc[11] += kd * v2.w;
            acc[12] += kd * v3.x;  acc[13] += kd * v3.y;  acc[14] += kd * v3.z;  acc[15] += kd * v3.w;
        }
        __syncthreads();
    }
    size_t ob = ((size_t)nh * 8 + ch) * (CDH * CDH) + (size_t)d0 * CDH + mq;
#pragma unroll
    for (int j = 0; j < 16; j++) kvp[ob + j] = acc[j];
    if ((t & 3) == 0) ksp[((size_t)nh * 8 + ch) * CDH + d0] = ks;
}

__global__ void kv_reduce(const float* __restrict__ kvp, const float* __restrict__ ksp,
                          float* __restrict__ kv, float* __restrict__ ksum)
{
    int idx = blockIdx.x * 256 + threadIdx.x;
    const int NKV = CB * CH * CDH * CDH;
    if (idx < NKV) {
        int nh = idx >> 12, r = idx & 4095;
        float s = 0.f;
        for (int c = 0; c < 8; c++) s += kvp[((size_t)nh * 8 + c) * (CDH * CDH) + r];
        kv[idx] = s;
    } else if (idx < NKV + CB * CH * CDH) {
        int i2 = idx - NKV;
        int nh = i2 >> 6, r = i2 & 63;
        float s = 0.f;
        for (int c = 0; c < 8; c++) s += ksp[((size_t)nh * 8 + c) * CDH + r];
        ksum[i2] = s;
    }
}

// ---------------- attn -> split bf16 ----------------
__global__ __launch_bounds__(256) void attn_kernel(const float* __restrict__ Qf, const float* __restrict__ kv,
                                                   const float* __restrict__ ksum,
                                                   __nv_bfloat16* __restrict__ outh,
                                                   __nv_bfloat16* __restrict__ outl)
{
    int nh = blockIdx.x, ch = blockIdx.y;
    int n = nh >> 4, h = nh & 15;
    int t = threadIdx.x;
    __shared__ float skvt[64][68];
    __shared__ float sks[64];
    __shared__ float sq[4][64];
    for (int i = t; i < 4096; i += 256) {
        int d = i >> 6, m = i & 63;
        skvt[m][d] = kv[(size_t)nh * 4096 + i];
    }
    if (t < 64) sks[t] = ksum[(size_t)nh * 64 + t];
    __syncthreads();
    int g = t >> 6, m = t & 63;
    int s0 = ch * 257, s1 = min(s0 + 257, CT);
    for (int tt = s0; tt < s1; tt += 4) {
        int nr = min(4, s1 - tt);
        if (t < nr * 64)
            sq[t >> 6][t & 63] = Qf[(((size_t)n * CT + (tt + (t >> 6))) * CH + h) * CDH + (t & 63)];
        __syncthreads();
        if (g < nr) {
            float sm = 0.f, sz = 0.f;
#pragma unroll
            for (int d = 0; d < 64; d += 4) {
                float4 q4 = *(const float4*)&sq[g][d];
                float4 k4 = *(const float4*)&skvt[m][d];
                float4 z4 = *(const float4*)&sks[d];
                sm += q4.x * k4.x + q4.y * k4.y + q4.z * k4.z + q4.w * k4.w;
                sz += q4.x * z4.x + q4.y * z4.y + q4.z * z4.z + q4.w * z4.w;
            }
            float r = sm / (sz + 1e-6f);
            size_t o = (((size_t)n * CT + (tt + g)) * CH + h) * CDH + m;
            split_store1(r, outh + o, outl + o);
        }
        __syncthreads();
    }
}

// ---------------- residual + LN (in place) + split ----------------
__global__ __launch_bounds__(256) void ln_kernel(float* __restrict__ x, const float* __restrict__ res,
                                                 const float* __restrict__ g, const float* __restrict__ b,
                                                 __nv_bfloat16* __restrict__ ph, __nv_bfloat16* __restrict__ pl)
{
    int row = blockIdx.x;
    int t = threadIdx.x;
    size_t base = (size_t)row * CD + t * 4;
    float4 a = *(const float4*)(x + base);
    float4 r = *(const float4*)(res + base);
    a.x += r.x; a.y += r.y; a.z += r.z; a.w += r.w;
    float s  = a.x + a.y + a.z + a.w;
    float ss = a.x * a.x + a.y * a.y + a.z * a.z + a.w * a.w;
#pragma unroll
    for (int o = 16; o > 0; o >>= 1) {
        s  += __shfl_xor_sync(0xffffffffu, s,  o);
        ss += __shfl_xor_sync(0xffffffffu, ss, o);
    }
    __shared__ float sh[18];
    int w = t >> 5;
    if ((t & 31) == 0) { sh[w] = s; sh[8 + w] = ss; }
    __syncthreads();
    if (t == 0) {
        float S = 0.f, SS = 0.f;
        for (int i = 0; i < 8; i++) { S += sh[i]; SS += sh[8 + i]; }
        float m = S * (1.f / CD);
        sh[16] = m;
        sh[17] = rsqrtf(SS * (1.f / CD) - m * m + 1e-5f);
    }
    __syncthreads();
    float m = sh[16], inv = sh[17];
    float4 gg = *(const float4*)(g + t * 4);
    float4 bb = *(const float4*)(b + t * 4);
    float4 o;
    o.x = (a.x - m) * inv * gg.x + bb.x;
    o.y = (a.y - m) * inv * gg.y + bb.y;
    o.z = (a.z - m) * inv * gg.z + bb.z;
    o.w = (a.w - m) * inv * gg.w + bb.w;
    *(float4*)(x + base) = o;
    split_store4(o, ph + base, pl + base);
}

// ---------------- final LN on CLS rows ----------------
__global__ __launch_bounds__(256) void ln_cls_kernel(const float* __restrict__ x, const float* __restrict__ g,
                                                     const float* __restrict__ b, float* __restrict__ outp)
{
    int n = blockIdx.x;
    int t = threadIdx.x;
    size_t base = (size_t)n * CT * CD + t * 4;
    float4 a = *(const float4*)(x + base);
    float s  = a.x + a.y + a.z + a.w;
    float ss = a.x * a.x + a.y * a.y + a.z * a.z + a.w * a.w;
#pragma unroll
    for (int o = 16; o > 0; o >>= 1) {
        s  += __shfl_xor_sync(0xffffffffu, s,  o);
        ss += __shfl_xor_sync(0xffffffffu, ss, o);
    }
    __shared__ float sh[18];
    int w = t >> 5;
    if ((t & 31) == 0) { sh[w] = s; sh[8 + w] = ss; }
    __syncthreads();
    if (t == 0) {
        float S = 0.f, SS = 0.f;
        for (int i = 0; i < 8; i++) { S += sh[i]; SS += sh[8 + i]; }
        float m = S * (1.f / CD);
        sh[16] = m;
        sh[17] = rsqrtf(SS * (1.f / CD) - m * m + 1e-5f);
    }
    __syncthreads();
    float m = sh[16], inv = sh[17];
    float4 gg = *(const float4*)(g + t * 4);
    float4 bb = *(const float4*)(b + t * 4);
    float4 o;
    o.x = (a.x - m) * inv * gg.x + bb.x;
    o.y = (a.y - m) * inv * gg.y + bb.y;
    o.z = (a.z - m) * inv * gg.z + bb.z;
    o.w = (a.w - m) * inv * gg.w + bb.w;
    *(float4*)(outp + (size_t)n * CD + t * 4) = o;
}

// ---------------- output head ----------------
__global__ __launch_bounds__(256) void out_kernel(const float* __restrict__ xc, const float* __restrict__ Wout,
                                                  const float* __restrict__ bout, float* __restrict__ out)
{
    int c = blockIdx.x * 256 + threadIdx.x;
    __shared__ float sx[CB][CD];
    for (int i = threadIdx.x; i < CB * CD; i += 256)
        sx[i >> 10][i & 1023] = xc[i];
    __syncthreads();
    float acc[CB];
#pragma unroll
    for (int n = 0; n < CB; n++) acc[n] = bout[c];
    for (int d = 0; d < CD; d++) {
        float wv = Wout[(size_t)d * CV + c];
#pragma unroll
        for (int n = 0; n < CB; n++) acc[n] += sx[n][d] * wv;
    }
#pragma unroll
    for (int n = 0; n < CB; n++) out[(size_t)n * CV + c] = acc[n];
}

// ---------------- host ----------------
extern "C" void kernel_launch(void* const* d_in, const int* in_sizes, int n_in,
                              void* d_out, int out_size)
{
    (void)in_sizes; (void)n_in; (void)out_size;
    const float* inputs = (const float*)d_in[0];
    const float* We   = (const float*)d_in[1];
    const float* be   = (const float*)d_in[2];
    const float* pos  = (const float*)d_in[3];
    const float* Wq   = (const float*)d_in[4];
    const float* bq   = (const float*)d_in[5];
    const float* Wk   = (const float*)d_in[6];
    const float* bk   = (const float*)d_in[7];
    const float* Wv   = (const float*)d_in[8];
    const float* bv   = (const float*)d_in[9];
    const float* Wo   = (const float*)d_in[10];
    const float* bo   = (const float*)d_in[11];
    const float* ln1g = (const float*)d_in[12];
    const float* ln1b = (const float*)d_in[13];
    const float* W1   = (const float*)d_in[14];
    const float* b1   = (const float*)d_in[15];
    const float* W2   = (const float*)d_in[16];
    const float* b2   = (const float*)d_in[17];
    const float* ln2g = (const float*)d_in[18];
    const float* ln2b = (const float*)d_in[19];
    const float* gN   = (const float*)d_in[20];
    const float* bN   = (const float*)d_in[21];
    const float* Wout = (const float*)d_in[22];
    const float* bout = (const float*)d_in[23];
    float* out = (float*)d_out;

    float *x, *q, *k, *v, *tmp, *kvp, *ksp, *kv, *ksum, *clsb;
    __nv_bfloat16 *wh, *wl, *sxh, *sxl, *axh, *axl, *sfh, *sfl;
    cudaGetSymbolAddress((void**)&x,    g_x);
    cudaGetSymbolAddress((void**)&q,    g_q);
    cudaGetSymbolAddress((void**)&k,    g_k);
    cudaGetSymbolAddress((void**)&v,    g_v);
    cudaGetSymbolAddress((void**)&tmp,  g_tmp);
    cudaGetSymbolAddress((void**)&kvp,  g_kvp);
    cudaGetSymbolAddress((void**)&ksp,  g_ksp);
    cudaGetSymbolAddress((void**)&kv,   g_kv);
    cudaGetSymbolAddress((void**)&ksum, g_ksum);
    cudaGetSymbolAddress((void**)&clsb, g_cls);
    cudaGetSymbolAddress((void**)&wh,   g_wh);
    cudaGetSymbolAddress((void**)&wl,   g_wl);
    cudaGetSymbolAddress((void**)&sxh,  g_sxh);
    cudaGetSymbolAddress((void**)&sxl,  g_sxl);
    cudaGetSymbolAddress((void**)&axh,  g_axh);
    cudaGetSymbolAddress((void**)&axl,  g_axl);
    cudaGetSymbolAddress((void**)&sfh,  g_sfh);
    cudaGetSymbolAddress((void**)&sfl,  g_sfl);

    cudaFuncSetAttribute(tgemm<0>, cudaFuncAttributeMaxDynamicSharedMemorySize, TG_SMEM);
    cudaFuncSetAttribute(tgemm<1>, cudaFuncAttributeMaxDynamicSharedMemorySize, TG_SMEM);
    cudaFuncSetAttribute(tgemm<2>, cudaFuncAttributeMaxDynamicSharedMemorySize, TG_SMEM);

    // ---- preprocess: split inputs, transpose+split all weights ----
    split_in<<<65536, 256>>>(inputs, sfh, sfl);
    split_w<<<dim3(CD / 32, CV / 32), 256>>>(We, wh + W_WE, wl + W_WE, CV, CD);
    for (int l = 0; l < CNL; l++) {
        split_w<<<dim3(CD / 32, CD / 32), 256>>>(Wq + (size_t)l * CD * CD, wh + W_Q(l), wl + W_Q(l), CD, CD);
        split_w<<<dim3(CD / 32, CD / 32), 256>>>(Wk + (size_t)l * CD * CD, wh + W_K(l), wl + W_K(l), CD, CD);
        split_w<<<dim3(CD / 32, CD / 32), 256>>>(Wv + (size_t)l * CD * CD, wh + W_V(l), wl + W_V(l), CD, CD);
        split_w<<<dim3(CD / 32, CD / 32), 256>>>(Wo + (size_t)l * CD * CD, wh + W_O(l), wl + W_O(l), CD, CD);
        split_w<<<dim3(CFF / 32, CD / 32), 256>>>(W1 + (size_t)l * CD * CFF, wh + W_W1(l), wl + W_W1(l), CD, CFF);
        split_w<<<dim3(CD / 32, CFF / 32), 256>>>(W2 + (size_t)l * CFF * CD, wh + W_W2(l), wl + W_W2(l), CFF, CD);
    }

    // ---- embedding GEMM [16384,4096]@[4096,1024]^T -> x (+split) ----
    tgemm<2><<<dim3(CD / 128, 128), 256, TG_SMEM>>>(
        sfh, sfl, wh + W_WE, wl + W_WE, be, pos, x, sxh, sxl, CB * CSEQ, CD, CV);
    cls_kernel<<<(CB * CD + 255) / 256, 256>>>(We, be, pos, x, sxh, sxl);

    const int M = CM;
    dim3 gDD(CD / 128, (M + 127) / 128);
    dim3 gDF(CFF / 128, (M + 127) / 128);

    for (int l = 0; l < CNL; l++) {
        tgemm<0><<<gDD, 256, TG_SMEM>>>(sxh, sxl, wh + W_Q(l), wl + W_Q(l),
            bq + (size_t)l * CD, nullptr, q, nullptr, nullptr, M, CD, CD);
        tgemm<0><<<gDD, 256, TG_SMEM>>>(sxh, sxl, wh + W_K(l), wl + W_K(l),
            bk + (size_t)l * CD, nullptr, k, nullptr, nullptr, M, CD, CD);
        tgemm<0><<<gDD, 256, TG_SMEM>>>(sxh, sxl, wh + W_V(l), wl + W_V(l),
            bv + (size_t)l * CD, nullptr, v, nullptr, nullptr, M, CD, CD);

        rope_phi_kernel<<<(CB * CT * CH * 32 + 255) / 256, 256>>>(q, k);
        kv_partial<<<dim3(CB * CH, 8), 256>>>(k, v, kvp, ksp);
        kv_reduce<<<(CB * CH * CDH * CDH + CB * CH * CDH + 255) / 256, 256>>>(kvp, ksp, kv, ksum);
        attn_kernel<<<dim3(CB * CH, 8), 256>>>(q, kv, ksum, axh, axl);

        tgemm<0><<<gDD, 256, TG_SMEM>>>(axh, axl, wh + W_O(l), wl + W_O(l),
            bo + (size_t)l * CD, nullptr, tmp, nullptr, nullptr, M, CD, CD);
        ln_kernel<<<M, 256>>>(x, tmp, ln1g + (size_t)l * CD, ln1b + (size_t)l * CD, sxh, sxl);

        tgemm<1><<<gDF, 256, TG_SMEM>>>(sxh, sxl, wh + W_W1(l), wl + W_W1(l),
            b1 + (size_t)l * CFF, nullptr, nullptr, sfh, sfl, M, CFF, CD);
        tgemm<0><<<gDD, 256, TG_SMEM>>>(sfh, sfl, wh + W_W2(l), wl + W_W2(l),
            b2 + (size_t)l * CD, nullptr, tmp, nullptr, nullptr, M, CD, CFF);
        ln_kernel<<<M, 256>>>(x, tmp, ln2g + (size_t)l * CD, ln2b + (size_t)l * CD, sxh, sxl);
    }

    ln_cls_kernel<<<CB, 256>>>(x, gN, bN, clsb);
    out_kernel<<<CV / 256, 256>>>(clsb, Wout, bout, out);
}